// round 4
// baseline (speedup 1.0000x reference)
#include <cuda_runtime.h>
#include <cuda_bf16.h>
#include <math.h>

#define C    24
#define HC   96
#define FT   48
#define NPOS (FT*FT)
#define P    16           // positions per block (144 blocks = 1 wave on 148 SMs)
#define NBLK (NPOS / P)   // 144
#define XNORM_A 0.007843137718737125f
#define DELTA 1.8f
#define OUT_SCALE 0.02083333395421505f

// Dense head outputs (raw logits / raw values), channel-major [ch][pos]
__device__ float g_hmhp[17 * NPOS];
__device__ float g_hps[34 * NPOS];
__device__ float g_off[34 * NPOS];
// Per-block center argmax partials: key = (score_bits<<32) | (0xFFFFFFFF - pos)
__device__ unsigned long long g_part[NBLK];
// Completion counters (self-resetting each launch)
__device__ int g_count = 0;
__device__ int g_done  = 0;

__device__ __forceinline__ float fast_sig(float v) {
    return __fdividef(1.0f, 1.0f + __expf(-v));
}

// ---------------------------------------------------------------------------
// Fused kernel: 144 blocks x 256 threads.
//   All blocks: dense 4-head evaluation for their 16 positions + center key.
//   Blocks 0..16: spin for completion, then decode keypoint blockIdx.x.
// ---------------------------------------------------------------------------
__global__ __launch_bounds__(256) void fused_kernel(
    const float* __restrict__ x,
    const float* __restrict__ w_dw0, const float* __restrict__ b_dw0,  // hm_hp
    const float* __restrict__ w1_0,  const float* __restrict__ b1_0,
    const float* __restrict__ w2_0,  const float* __restrict__ b2_0,
    const float* __restrict__ w_dw1, const float* __restrict__ b_dw1,  // hm
    const float* __restrict__ w1_1,  const float* __restrict__ b1_1,
    const float* __restrict__ w2_1,  const float* __restrict__ b2_1,
    const float* __restrict__ w_dw2, const float* __restrict__ b_dw2,  // hps
    const float* __restrict__ w1_2,  const float* __restrict__ b1_2,
    const float* __restrict__ w2_2,  const float* __restrict__ b2_2,
    const float* __restrict__ w_dw3, const float* __restrict__ b_dw3,  // hp_offset
    const float* __restrict__ w1_3,  const float* __restrict__ b1_3,
    const float* __restrict__ w2_3,  const float* __restrict__ b2_3,
    float* __restrict__ out)
{
    __shared__ float xs[C][3][P + 2];     // normalized input tile (zero padded)
    __shared__ float ys[4][P][28];        // depthwise outputs, padded stride
    __shared__ float zs[4][P][100];       // pw1+relu outputs, padded stride
    __shared__ unsigned long long skey[P];
    __shared__ float s_v[8];
    __shared__ int   s_i[8];
    __shared__ int   s_ct, s_top;
    __shared__ float s_kc[2];

    const int tid   = threadIdx.x;
    const int lane  = tid & 31;
    const int wid   = tid >> 5;
    const int pbase = blockIdx.x * P;     // 48 % 16 == 0 -> all same row
    const int row   = pbase / FT;
    const int col0  = pbase % FT;

    // ---- stage X: normalized 3x(P+2) neighborhood, all 24 channels
    for (int idx = tid; idx < C * 3 * (P + 2); idx += 256) {
        int c  = idx / (3 * (P + 2));
        int r  = (idx / (P + 2)) % 3;
        int cc = idx % (P + 2);
        int gi = row + r - 1;
        int gj = col0 + cc - 1;
        float v = 0.f;
        if (gi >= 0 && gi < FT && gj >= 0 && gj < FT)
            v = x[(c * FT + gi) * FT + gj] * XNORM_A - 1.0f;
        xs[c][r][cc] = v;
    }
    __syncthreads();

    // ---- stage Y: depthwise 3x3, 4 heads: 4*24*16 = 1536 values
    for (int idx = tid; idx < 4 * C * P; idx += 256) {
        int h   = idx / (C * P);
        int rem = idx % (C * P);
        int c   = rem / P;
        int p   = rem % P;
        const float* wd = (h == 0) ? w_dw0 : (h == 1) ? w_dw1 : (h == 2) ? w_dw2 : w_dw3;
        const float* bd = (h == 0) ? b_dw0 : (h == 1) ? b_dw1 : (h == 2) ? b_dw2 : b_dw3;
        float acc = bd[c];
        #pragma unroll
        for (int r = 0; r < 3; r++)
            #pragma unroll
            for (int s = 0; s < 3; s++)
                acc += wd[c * 9 + r * 3 + s] * xs[c][r][p + s];
        ys[h][p][c] = acc;
    }
    __syncthreads();

    // ---- stage Z: pw1 (24->96) + bias + relu, 4 heads: 384 rows
    for (int rrow = tid; rrow < 4 * HC; rrow += 256) {
        int h  = rrow / HC;
        int oc = rrow % HC;
        const float* w1 = (h == 0) ? w1_0 : (h == 1) ? w1_1 : (h == 2) ? w1_2 : w1_3;
        const float* b1 = (h == 0) ? b1_0 : (h == 1) ? b1_1 : (h == 2) ? b1_2 : b1_3;
        float acc[P];
        float b = b1[oc];
        #pragma unroll
        for (int p = 0; p < P; p++) acc[p] = b;
        #pragma unroll
        for (int k = 0; k < C; k++) {
            float wv = __ldg(&w1[oc * C + k]);
            #pragma unroll
            for (int p = 0; p < P; p++) acc[p] += wv * ys[h][p][k];
        }
        #pragma unroll
        for (int p = 0; p < P; p++) zs[h][p][oc] = fmaxf(acc[p], 0.f);
    }
    __syncthreads();

    // ---- stage O: pw2. combos: hm_hp 17 | hm 1 | hps 34 | off 34 = 86
    for (int idx = tid; idx < 86 * P; idx += 256) {
        int combo = idx / P;
        int p     = idx % P;
        int pos   = pbase + p;
        int h, oc;
        const float *w2, *b2;
        float* dst;
        if (combo < 17)       { h = 0; oc = combo;      w2 = w2_0; b2 = b2_0; dst = g_hmhp; }
        else if (combo == 17) { h = 1; oc = 0;          w2 = w2_1; b2 = b2_1; dst = 0;      }
        else if (combo < 52)  { h = 2; oc = combo - 18; w2 = w2_2; b2 = b2_2; dst = g_hps;  }
        else                  { h = 3; oc = combo - 52; w2 = w2_3; b2 = b2_3; dst = g_off;  }
        float acc = b2[oc];
        #pragma unroll 8
        for (int k = 0; k < HC; k++)
            acc += __ldg(&w2[oc * HC + k]) * zs[h][p][k];
        if (dst) {
            dst[oc * NPOS + pos] = acc;
        } else {
            // hm logit -> center-weighted score -> order-encoded key
            float sig = fast_sig(acc);
            float gy = (float)row - (FT * 0.5f);
            float gx = (float)(col0 + p) - (FT * 0.5f);
            float s = __fdividef(sig, sqrtf(gy * gy + gx * gx) + DELTA);
            skey[p] = ((unsigned long long)__float_as_uint(s) << 32)
                    | (unsigned long long)(0xFFFFFFFFu - (unsigned)pos);
        }
    }
    __syncthreads();
    if (tid == 0) {
        unsigned long long best = skey[0];
        #pragma unroll
        for (int p = 1; p < P; p++) if (skey[p] > best) best = skey[p];
        g_part[blockIdx.x] = best;
    }

    // ---- publish: all global writes visible, then signal
    __threadfence();
    __syncthreads();
    if (tid == 0) atomicAdd(&g_count, 1);

    if (blockIdx.x >= 17) return;   // head-only blocks done

    // =======================================================================
    // Decode for keypoint k = blockIdx.x
    // =======================================================================
    const int k = blockIdx.x;

    if (tid == 0) {
        while (atomicAdd(&g_count, 0) < NBLK) __nanosleep(64);
    }
    __syncthreads();
    __threadfence();

    // ---- A: reduce 144 per-block center keys (warp 0)
    if (wid == 0) {
        unsigned long long key = 0ULL;
        for (int i = lane; i < NBLK; i += 32) {
            unsigned long long v = g_part[i];
            if (v > key) key = v;
        }
        #pragma unroll
        for (int off = 16; off; off >>= 1) {
            unsigned long long o = __shfl_down_sync(0xffffffffu, key, off);
            if (o > key) key = o;
        }
        if (lane == 0)
            s_ct = (int)(0xFFFFFFFFu - (unsigned)(key & 0xFFFFFFFFu));
    }
    __syncthreads();
    const int ct  = s_ct;
    const int cty = ct / FT, ctx = ct % FT;

    // ---- B: kpt_coor from dense hps
    if (tid < 2)
        s_kc[tid] = g_hps[(2 * k + tid) * NPOS + ct] + (tid ? (float)ctx : (float)cty);
    __syncthreads();

    // ---- C: distance-weighted argmax over this keypoint's heatmap
    const float ky = s_kc[0];
    const float kx = s_kc[1];
    const float* hmap = g_hmhp + k * NPOS;
    {
        float bv = -1e30f; int bi = 0x7fffffff;
        #pragma unroll
        for (int i = 0; i < NPOS / 256; i++) {
            int p = tid + i * 256;
            float sig = fast_sig(__ldg(&hmap[p]));
            int py = p / FT;
            float dy = (float)py - ky;
            float dx = (float)(p - py * FT) - kx;
            float s = __fdividef(sig, sqrtf(dy * dy + dx * dx) + DELTA);
            if (s > bv || (s == bv && p < bi)) { bv = s; bi = p; }
        }
        #pragma unroll
        for (int off = 16; off; off >>= 1) {
            float ov = __shfl_down_sync(0xffffffffu, bv, off);
            int   oi = __shfl_down_sync(0xffffffffu, bi, off);
            if (ov > bv || (ov == bv && oi < bi)) { bv = ov; bi = oi; }
        }
        if (lane == 0) { s_v[wid] = bv; s_i[wid] = bi; }
        __syncthreads();
        if (tid == 0) {
            float xv = s_v[0]; int xi = s_i[0];
            #pragma unroll
            for (int w = 1; w < 8; w++) {
                if (s_v[w] > xv || (s_v[w] == xv && s_i[w] < xi)) {
                    xv = s_v[w]; xi = s_i[w];
                }
            }
            s_top = xi;
        }
        __syncthreads();
    }
    const int top = s_top;
    const int ty  = top / FT, tx = top % FT;

    // ---- D: outputs from dense hp_offset
    if (tid < 2) {
        float o = g_off[(2 * k + tid) * NPOS + top];
        float base = tid ? (float)tx : (float)ty;
        out[k * 3 + tid] = (o + base) * OUT_SCALE;
    }
    if (tid == 2)   // precise sigmoid for reported confidence
        out[k * 3 + 2] = 1.0f / (1.0f + expf(-hmap[top]));

    // ---- completion + counter reset for graph replay determinism
    __syncthreads();
    if (tid == 0) atomicAdd(&g_done, 1);
    if (k == 0 && tid == 0) {
        while (atomicAdd(&g_done, 0) < 17) __nanosleep(32);
        atomicExch(&g_count, 0);
        atomicExch(&g_done, 0);
    }
}

// ---------------------------------------------------------------------------
extern "C" void kernel_launch(void* const* d_in, const int* in_sizes, int n_in,
                              void* d_out, int out_size)
{
    fused_kernel<<<NBLK, 256>>>(
        (const float*)d_in[0],
        (const float*)d_in[1],  (const float*)d_in[2],
        (const float*)d_in[3],  (const float*)d_in[4],
        (const float*)d_in[5],  (const float*)d_in[6],
        (const float*)d_in[7],  (const float*)d_in[8],
        (const float*)d_in[9],  (const float*)d_in[10],
        (const float*)d_in[11], (const float*)d_in[12],
        (const float*)d_in[13], (const float*)d_in[14],
        (const float*)d_in[15], (const float*)d_in[16],
        (const float*)d_in[17], (const float*)d_in[18],
        (const float*)d_in[19], (const float*)d_in[20],
        (const float*)d_in[21], (const float*)d_in[22],
        (const float*)d_in[23], (const float*)d_in[24],
        (float*)d_out);
}

// round 5
// speedup vs baseline: 1.2745x; 1.2745x over previous
#include <cuda_runtime.h>
#include <cuda_bf16.h>
#include <math.h>

#define C    24
#define HC   96
#define FT   48
#define NPOS (FT*FT)
#define P    16           // positions per block (144 blocks = 1 wave on 148 SMs)
#define NBLK (NPOS / P)   // 144
#define XNORM_A 0.007843137718737125f
#define DELTA 1.8f
#define OUT_SCALE 0.02083333395421505f

// Dense head outputs needed by decode (raw logits), channel-major [ch][pos]
__device__ float g_hmhp[17 * NPOS];
// Per-block center argmax partials: key = (score_bits<<32) | (0xFFFFFFFF - pos)
__device__ unsigned long long g_part[NBLK];
// Completion counters (self-resetting each launch)
__device__ int g_count = 0;
__device__ int g_done  = 0;

__device__ __forceinline__ float fast_sig(float v) {
    return __fdividef(1.0f, 1.0f + __expf(-v));
}

// depthwise-3x3 at a single position/channel, with input normalization + zero pad
__device__ __forceinline__ float dw_at(const float* __restrict__ x,
                                       const float* __restrict__ wd,
                                       const float* __restrict__ bd,
                                       int c, int i, int j)
{
    float acc = bd[c];
    #pragma unroll
    for (int r = 0; r < 3; r++) {
        int gi = i + r - 1;
        if (gi < 0 || gi >= FT) continue;
        #pragma unroll
        for (int s = 0; s < 3; s++) {
            int gj = j + s - 1;
            if (gj < 0 || gj >= FT) continue;
            float xv = x[(c * FT + gi) * FT + gj] * XNORM_A - 1.0f;
            acc += wd[c * 9 + r * 3 + s] * xv;
        }
    }
    return acc;
}

// ---------------------------------------------------------------------------
// Fused kernel: 144 blocks x 256 threads, single wave.
//   All blocks: dense hm_hp(17) + hm(1) heads for their 16 positions.
//   Blocks 0..16: spin until all heads done, then decode keypoint blockIdx.x
//   (lazy hps head at the center, lazy hp_offset head at the winner).
// ---------------------------------------------------------------------------
__global__ __launch_bounds__(256) void fused_kernel(
    const float* __restrict__ x,
    const float* __restrict__ w_dw0, const float* __restrict__ b_dw0,  // hm_hp
    const float* __restrict__ w1_0,  const float* __restrict__ b1_0,
    const float* __restrict__ w2_0,  const float* __restrict__ b2_0,
    const float* __restrict__ w_dw1, const float* __restrict__ b_dw1,  // hm
    const float* __restrict__ w1_1,  const float* __restrict__ b1_1,
    const float* __restrict__ w2_1,  const float* __restrict__ b2_1,
    const float* __restrict__ hps_dw_w, const float* __restrict__ hps_dw_b,
    const float* __restrict__ hps_w1,   const float* __restrict__ hps_b1,
    const float* __restrict__ hps_w2,   const float* __restrict__ hps_b2,
    const float* __restrict__ off_dw_w, const float* __restrict__ off_dw_b,
    const float* __restrict__ off_w1,   const float* __restrict__ off_b1,
    const float* __restrict__ off_w2,   const float* __restrict__ off_b2,
    float* __restrict__ out)
{
    __shared__ float xs[C][3][P + 2];     // normalized input tile (zero padded)
    __shared__ float ys[2][P][28];        // depthwise outputs, padded stride
    __shared__ float zs[2][P][100];       // pw1+relu outputs, padded stride
    __shared__ unsigned long long skey[P];
    __shared__ float s_v[8];
    __shared__ int   s_i[8];
    __shared__ int   s_ct, s_top;
    __shared__ float s_y[C];
    __shared__ float s_z[HC];
    __shared__ float s_kc[2];

    const int tid   = threadIdx.x;
    const int lane  = tid & 31;
    const int wid   = tid >> 5;
    const int pbase = blockIdx.x * P;     // 48 % 16 == 0 -> all same row
    const int row   = pbase / FT;
    const int col0  = pbase % FT;

    // ======================= dense heads (all 144 blocks) ==================
    // ---- stage X
    for (int idx = tid; idx < C * 3 * (P + 2); idx += 256) {
        int c  = idx / (3 * (P + 2));
        int r  = (idx / (P + 2)) % 3;
        int cc = idx % (P + 2);
        int gi = row + r - 1;
        int gj = col0 + cc - 1;
        float v = 0.f;
        if (gi >= 0 && gi < FT && gj >= 0 && gj < FT)
            v = x[(c * FT + gi) * FT + gj] * XNORM_A - 1.0f;
        xs[c][r][cc] = v;
    }
    __syncthreads();

    // ---- stage Y: depthwise 3x3, 2 heads: 2*24*16 = 768 values
    for (int idx = tid; idx < 2 * C * P; idx += 256) {
        int h   = idx / (C * P);
        int rem = idx % (C * P);
        int c   = rem / P;
        int p   = rem % P;
        const float* wd = h ? w_dw1 : w_dw0;
        const float* bd = h ? b_dw1 : b_dw0;
        float acc = bd[c];
        #pragma unroll
        for (int r = 0; r < 3; r++)
            #pragma unroll
            for (int s = 0; s < 3; s++)
                acc += wd[c * 9 + r * 3 + s] * xs[c][r][p + s];
        ys[h][p][c] = acc;
    }
    __syncthreads();

    // ---- stage Z: pw1 (24->96) + relu, 2 heads: 192 rows (<=1 per thread)
    if (tid < 2 * HC) {
        int h  = tid / HC;
        int oc = tid % HC;
        const float* w1 = h ? w1_1 : w1_0;
        const float* b1 = h ? b1_1 : b1_0;
        float acc[P];
        float b = b1[oc];
        #pragma unroll
        for (int p = 0; p < P; p++) acc[p] = b;
        #pragma unroll
        for (int k = 0; k < C; k++) {
            float wv = __ldg(&w1[oc * C + k]);
            #pragma unroll
            for (int p = 0; p < P; p++) acc[p] += wv * ys[h][p][k];
        }
        #pragma unroll
        for (int p = 0; p < P; p++) zs[h][p][oc] = fmaxf(acc[p], 0.f);
    }
    __syncthreads();

    // ---- stage O: pw2. hm_hp 17ch + hm 1ch = 18*16 = 288 items
    for (int idx = tid; idx < 18 * P; idx += 256) {
        int combo = idx / P;
        int p     = idx % P;
        int pos   = pbase + p;
        if (combo < 17) {
            int oc = combo;
            float acc = b2_0[oc];
            #pragma unroll 8
            for (int k = 0; k < HC; k++)
                acc += __ldg(&w2_0[oc * HC + k]) * zs[0][p][k];
            g_hmhp[oc * NPOS + pos] = acc;
        } else {
            float acc = b2_1[0];
            #pragma unroll 8
            for (int k = 0; k < HC; k++)
                acc += __ldg(&w2_1[k]) * zs[1][p][k];
            float sig = fast_sig(acc);
            float gy = (float)row - (FT * 0.5f);
            float gx = (float)(col0 + p) - (FT * 0.5f);
            float s = __fdividef(sig, sqrtf(gy * gy + gx * gx) + DELTA);
            skey[p] = ((unsigned long long)__float_as_uint(s) << 32)
                    | (unsigned long long)(0xFFFFFFFFu - (unsigned)pos);
        }
    }
    __syncthreads();
    if (tid == 0) {
        unsigned long long best = skey[0];
        #pragma unroll
        for (int p = 1; p < P; p++) if (skey[p] > best) best = skey[p];
        g_part[blockIdx.x] = best;
    }

    // ---- publish
    __threadfence();
    __syncthreads();
    if (tid == 0) atomicAdd(&g_count, 1);

    if (blockIdx.x >= 17) return;   // head-only blocks done

    // ======================= decode (blocks 0..16) =========================
    const int k = blockIdx.x;

    if (tid == 0) {
        while (atomicAdd(&g_count, 0) < NBLK) __nanosleep(64);
    }
    __syncthreads();
    __threadfence();

    // ---- A: reduce 144 per-block center keys (warp 0)
    if (wid == 0) {
        unsigned long long key = 0ULL;
        for (int i = lane; i < NBLK; i += 32) {
            unsigned long long v = g_part[i];
            if (v > key) key = v;
        }
        #pragma unroll
        for (int off = 16; off; off >>= 1) {
            unsigned long long o = __shfl_down_sync(0xffffffffu, key, off);
            if (o > key) key = o;
        }
        if (lane == 0)
            s_ct = (int)(0xFFFFFFFFu - (unsigned)(key & 0xFFFFFFFFu));
    }
    __syncthreads();
    const int ct  = s_ct;
    const int cty = ct / FT, ctx = ct % FT;

    // ---- B: hps head at the center (channels 2k, 2k+1)
    if (tid < C)
        s_y[tid] = dw_at(x, hps_dw_w, hps_dw_b, tid, cty, ctx);
    __syncthreads();
    if (tid < HC) {
        float a = hps_b1[tid];
        #pragma unroll
        for (int kk = 0; kk < C; kk++) a += __ldg(&hps_w1[tid * C + kk]) * s_y[kk];
        s_z[tid] = fmaxf(a, 0.f);
    }
    __syncthreads();
    if (wid < 2) {
        int oc = 2 * k + wid;
        float a = __ldg(&hps_w2[oc * HC + lane])      * s_z[lane]
                + __ldg(&hps_w2[oc * HC + lane + 32]) * s_z[lane + 32]
                + __ldg(&hps_w2[oc * HC + lane + 64]) * s_z[lane + 64];
        #pragma unroll
        for (int off = 16; off; off >>= 1)
            a += __shfl_down_sync(0xffffffffu, a, off);
        if (lane == 0)
            s_kc[wid] = a + hps_b2[oc] + (wid ? (float)ctx : (float)cty);
    }
    __syncthreads();

    // ---- C: distance-weighted argmax over this keypoint's heatmap
    const float ky = s_kc[0];
    const float kx = s_kc[1];
    const float* hmap = g_hmhp + k * NPOS;
    {
        float bv = -1e30f; int bi = 0x7fffffff;
        #pragma unroll
        for (int i = 0; i < NPOS / 256; i++) {
            int p = tid + i * 256;
            float sig = fast_sig(__ldg(&hmap[p]));
            int py = p / FT;
            float dy = (float)py - ky;
            float dx = (float)(p - py * FT) - kx;
            float s = __fdividef(sig, sqrtf(dy * dy + dx * dx) + DELTA);
            if (s > bv || (s == bv && p < bi)) { bv = s; bi = p; }
        }
        #pragma unroll
        for (int off = 16; off; off >>= 1) {
            float ov = __shfl_down_sync(0xffffffffu, bv, off);
            int   oi = __shfl_down_sync(0xffffffffu, bi, off);
            if (ov > bv || (ov == bv && oi < bi)) { bv = ov; bi = oi; }
        }
        if (lane == 0) { s_v[wid] = bv; s_i[wid] = bi; }
        __syncthreads();
        if (tid == 0) {
            float xv = s_v[0]; int xi = s_i[0];
            #pragma unroll
            for (int w = 1; w < 8; w++) {
                if (s_v[w] > xv || (s_v[w] == xv && s_i[w] < xi)) {
                    xv = s_v[w]; xi = s_i[w];
                }
            }
            s_top = xi;
        }
        __syncthreads();
    }
    const int top = s_top;
    const int ty  = top / FT, tx = top % FT;

    // ---- D: hp_offset head at the winner (channels 2k, 2k+1) + outputs
    if (tid < C)
        s_y[tid] = dw_at(x, off_dw_w, off_dw_b, tid, ty, tx);
    __syncthreads();
    if (tid < HC) {
        float a = off_b1[tid];
        #pragma unroll
        for (int kk = 0; kk < C; kk++) a += __ldg(&off_w1[tid * C + kk]) * s_y[kk];
        s_z[tid] = fmaxf(a, 0.f);
    }
    __syncthreads();
    if (wid < 2) {
        int oc = 2 * k + wid;
        float a = __ldg(&off_w2[oc * HC + lane])      * s_z[lane]
                + __ldg(&off_w2[oc * HC + lane + 32]) * s_z[lane + 32]
                + __ldg(&off_w2[oc * HC + lane + 64]) * s_z[lane + 64];
        #pragma unroll
        for (int off = 16; off; off >>= 1)
            a += __shfl_down_sync(0xffffffffu, a, off);
        if (lane == 0) {
            float base = wid ? (float)tx : (float)ty;
            out[k * 3 + wid] = (a + off_b2[oc] + base) * OUT_SCALE;
        }
    }
    if (tid == 64)   // precise sigmoid for reported confidence
        out[k * 3 + 2] = 1.0f / (1.0f + expf(-hmap[top]));

    // ---- completion + counter reset for graph replay determinism
    __syncthreads();
    if (tid == 0) atomicAdd(&g_done, 1);
    if (k == 0 && tid == 0) {
        while (atomicAdd(&g_done, 0) < 17) __nanosleep(32);
        atomicExch(&g_count, 0);
        atomicExch(&g_done, 0);
    }
}

// ---------------------------------------------------------------------------
extern "C" void kernel_launch(void* const* d_in, const int* in_sizes, int n_in,
                              void* d_out, int out_size)
{
    fused_kernel<<<NBLK, 256>>>(
        (const float*)d_in[0],
        (const float*)d_in[1],  (const float*)d_in[2],
        (const float*)d_in[3],  (const float*)d_in[4],
        (const float*)d_in[5],  (const float*)d_in[6],
        (const float*)d_in[7],  (const float*)d_in[8],
        (const float*)d_in[9],  (const float*)d_in[10],
        (const float*)d_in[11], (const float*)d_in[12],
        (const float*)d_in[13], (const float*)d_in[14],
        (const float*)d_in[15], (const float*)d_in[16],
        (const float*)d_in[17], (const float*)d_in[18],
        (const float*)d_in[19], (const float*)d_in[20],
        (const float*)d_in[21], (const float*)d_in[22],
        (const float*)d_in[23], (const float*)d_in[24],
        (float*)d_out);
}

// round 6
// speedup vs baseline: 1.2866x; 1.0094x over previous
#include <cuda_runtime.h>
#include <cuda_bf16.h>
#include <math.h>

#define C    24
#define HC   96
#define FT   48
#define NPOS (FT*FT)
#define P    16           // positions per block (144 blocks = 1 wave on 148 SMs)
#define NBLK (NPOS / P)   // 144
#define XNORM_A 0.007843137718737125f
#define DELTA 1.8f
#define OUT_SCALE 0.02083333395421505f

// Dense head outputs needed by decode (raw logits), channel-major [ch][pos]
__device__ float g_hmhp[17 * NPOS];
// Per-block center argmax partials: key = (score_bits<<32) | (0xFFFFFFFF - pos)
__device__ unsigned long long g_part[NBLK];
// Completion counters (self-resetting each launch)
__device__ int g_count = 0;
__device__ int g_done  = 0;

__device__ __forceinline__ float fast_sig(float v) {
    return __fdividef(1.0f, 1.0f + __expf(-v));
}

// depthwise-3x3 at a single position/channel, with input normalization + zero pad
__device__ __forceinline__ float dw_at(const float* __restrict__ x,
                                       const float* __restrict__ wd,
                                       const float* __restrict__ bd,
                                       int c, int i, int j)
{
    float acc = bd[c];
    #pragma unroll
    for (int r = 0; r < 3; r++) {
        int gi = i + r - 1;
        if (gi < 0 || gi >= FT) continue;
        #pragma unroll
        for (int s = 0; s < 3; s++) {
            int gj = j + s - 1;
            if (gj < 0 || gj >= FT) continue;
            float xv = __ldg(&x[(c * FT + gi) * FT + gj]) * XNORM_A - 1.0f;
            acc += __ldg(&wd[c * 9 + r * 3 + s]) * xv;
        }
    }
    return acc;
}

// ---------------------------------------------------------------------------
// Fused kernel: 144 blocks x 256 threads, single wave.
//   All blocks: dense hm_hp(17) + hm(1) heads for their 16 positions.
//   Blocks 0..16: prefetch decode weights into L1 at start (overlapped with
//   head compute), spin until all heads done, then decode keypoint blockIdx.x.
// ---------------------------------------------------------------------------
__global__ __launch_bounds__(256) void fused_kernel(
    const float* __restrict__ x,
    const float* __restrict__ w_dw0, const float* __restrict__ b_dw0,  // hm_hp
    const float* __restrict__ w1_0,  const float* __restrict__ b1_0,
    const float* __restrict__ w2_0,  const float* __restrict__ b2_0,
    const float* __restrict__ w_dw1, const float* __restrict__ b_dw1,  // hm
    const float* __restrict__ w1_1,  const float* __restrict__ b1_1,
    const float* __restrict__ w2_1,  const float* __restrict__ b2_1,
    const float* __restrict__ hps_dw_w, const float* __restrict__ hps_dw_b,
    const float* __restrict__ hps_w1,   const float* __restrict__ hps_b1,
    const float* __restrict__ hps_w2,   const float* __restrict__ hps_b2,
    const float* __restrict__ off_dw_w, const float* __restrict__ off_dw_b,
    const float* __restrict__ off_w1,   const float* __restrict__ off_b1,
    const float* __restrict__ off_w2,   const float* __restrict__ off_b2,
    float* __restrict__ out)
{
    __shared__ float xs[C][3][P + 2];     // normalized input tile (zero padded)
    __shared__ float ys[2][P][28];        // depthwise outputs, padded stride
    __shared__ float zs[2][P][100];       // pw1+relu outputs, padded stride
    __shared__ unsigned long long skey[P];
    __shared__ float s_v[8];
    __shared__ int   s_i[8];
    __shared__ int   s_ct, s_top;
    __shared__ float s_y[C];
    __shared__ float s_z[HC];
    __shared__ float s_kc[2];

    const int tid   = threadIdx.x;
    const int lane  = tid & 31;
    const int wid   = tid >> 5;
    const int pbase = blockIdx.x * P;     // 48 % 16 == 0 -> all same row
    const int row   = pbase / FT;
    const int col0  = pbase % FT;

    // ---- decode-weight L1 warming (blocks 0..16, overlapped with heads work)
    if (blockIdx.x < 17) {
        float acc = 0.f;
        for (int i = tid; i < HC * C; i += 256)
            acc += __ldg(&hps_w1[i]) + __ldg(&off_w1[i]);
        for (int i = tid; i < 34 * HC; i += 256)
            acc += __ldg(&hps_w2[i]) + __ldg(&off_w2[i]);
        for (int i = tid; i < C * 9; i += 256)
            acc += __ldg(&hps_dw_w[i]) + __ldg(&off_dw_w[i]);
        if (tid < HC) acc += __ldg(&hps_b1[tid]) + __ldg(&off_b1[tid]);
        if (tid < 34) acc += __ldg(&hps_b2[tid]) + __ldg(&off_b2[tid]);
        if (tid < C)  acc += __ldg(&hps_dw_b[tid]) + __ldg(&off_dw_b[tid]);
        asm volatile("" :: "f"(acc));     // keep the loads alive
    }

    // ======================= dense heads (all 144 blocks) ==================
    // ---- stage X
    for (int idx = tid; idx < C * 3 * (P + 2); idx += 256) {
        int c  = idx / (3 * (P + 2));
        int r  = (idx / (P + 2)) % 3;
        int cc = idx % (P + 2);
        int gi = row + r - 1;
        int gj = col0 + cc - 1;
        float v = 0.f;
        if (gi >= 0 && gi < FT && gj >= 0 && gj < FT)
            v = x[(c * FT + gi) * FT + gj] * XNORM_A - 1.0f;
        xs[c][r][cc] = v;
    }
    __syncthreads();

    // ---- stage Y: depthwise 3x3, 2 heads: 2*24*16 = 768 values
    for (int idx = tid; idx < 2 * C * P; idx += 256) {
        int h   = idx / (C * P);
        int rem = idx % (C * P);
        int c   = rem / P;
        int p   = rem % P;
        const float* wd = h ? w_dw1 : w_dw0;
        const float* bd = h ? b_dw1 : b_dw0;
        float acc = bd[c];
        #pragma unroll
        for (int r = 0; r < 3; r++)
            #pragma unroll
            for (int s = 0; s < 3; s++)
                acc += wd[c * 9 + r * 3 + s] * xs[c][r][p + s];
        ys[h][p][c] = acc;
    }
    __syncthreads();

    // ---- stage Z: pw1 (24->96) + relu, 2 heads: 192 rows (<=1 per thread)
    if (tid < 2 * HC) {
        int h  = tid / HC;
        int oc = tid % HC;
        const float* w1 = h ? w1_1 : w1_0;
        const float* b1 = h ? b1_1 : b1_0;
        float acc[P];
        float b = b1[oc];
        #pragma unroll
        for (int p = 0; p < P; p++) acc[p] = b;
        #pragma unroll
        for (int k = 0; k < C; k++) {
            float wv = __ldg(&w1[oc * C + k]);
            #pragma unroll
            for (int p = 0; p < P; p++) acc[p] += wv * ys[h][p][k];
        }
        #pragma unroll
        for (int p = 0; p < P; p++) zs[h][p][oc] = fmaxf(acc[p], 0.f);
    }
    __syncthreads();

    // ---- stage O: pw2. hm_hp 17ch + hm 1ch = 18*16 = 288 items
    for (int idx = tid; idx < 18 * P; idx += 256) {
        int combo = idx / P;
        int p     = idx % P;
        int pos   = pbase + p;
        if (combo < 17) {
            int oc = combo;
            float acc = b2_0[oc];
            #pragma unroll 8
            for (int k = 0; k < HC; k++)
                acc += __ldg(&w2_0[oc * HC + k]) * zs[0][p][k];
            g_hmhp[oc * NPOS + pos] = acc;
        } else {
            float acc = b2_1[0];
            #pragma unroll 8
            for (int k = 0; k < HC; k++)
                acc += __ldg(&w2_1[k]) * zs[1][p][k];
            float sig = fast_sig(acc);
            float gy = (float)row - (FT * 0.5f);
            float gx = (float)(col0 + p) - (FT * 0.5f);
            float s = __fdividef(sig, sqrtf(gy * gy + gx * gx) + DELTA);
            skey[p] = ((unsigned long long)__float_as_uint(s) << 32)
                    | (unsigned long long)(0xFFFFFFFFu - (unsigned)pos);
        }
    }
    __syncthreads();
    if (tid == 0) {
        unsigned long long best = skey[0];
        #pragma unroll
        for (int p = 1; p < P; p++) if (skey[p] > best) best = skey[p];
        g_part[blockIdx.x] = best;
    }

    // ---- publish
    __threadfence();
    __syncthreads();
    if (tid == 0) atomicAdd(&g_count, 1);

    if (blockIdx.x >= 17) return;   // head-only blocks done

    // ======================= decode (blocks 0..16) =========================
    const int k = blockIdx.x;

    if (tid == 0) {
        while (atomicAdd(&g_count, 0) < NBLK) __nanosleep(64);
    }
    __syncthreads();
    __threadfence();

    // ---- A: reduce 144 per-block center keys (warp 0)
    if (wid == 0) {
        unsigned long long key = 0ULL;
        for (int i = lane; i < NBLK; i += 32) {
            unsigned long long v = g_part[i];
            if (v > key) key = v;
        }
        #pragma unroll
        for (int off = 16; off; off >>= 1) {
            unsigned long long o = __shfl_down_sync(0xffffffffu, key, off);
            if (o > key) key = o;
        }
        if (lane == 0)
            s_ct = (int)(0xFFFFFFFFu - (unsigned)(key & 0xFFFFFFFFu));
    }
    __syncthreads();
    const int ct  = s_ct;
    const int cty = ct / FT, ctx = ct % FT;

    // ---- B: hps head at the center (channels 2k, 2k+1)
    if (tid < C)
        s_y[tid] = dw_at(x, hps_dw_w, hps_dw_b, tid, cty, ctx);
    __syncthreads();
    if (tid < HC) {
        float a = hps_b1[tid];
        #pragma unroll
        for (int kk = 0; kk < C; kk++) a += __ldg(&hps_w1[tid * C + kk]) * s_y[kk];
        s_z[tid] = fmaxf(a, 0.f);
    }
    __syncthreads();
    if (wid < 2) {
        int oc = 2 * k + wid;
        float a = __ldg(&hps_w2[oc * HC + lane])      * s_z[lane]
                + __ldg(&hps_w2[oc * HC + lane + 32]) * s_z[lane + 32]
                + __ldg(&hps_w2[oc * HC + lane + 64]) * s_z[lane + 64];
        #pragma unroll
        for (int off = 16; off; off >>= 1)
            a += __shfl_down_sync(0xffffffffu, a, off);
        if (lane == 0)
            s_kc[wid] = a + hps_b2[oc] + (wid ? (float)ctx : (float)cty);
    }
    __syncthreads();

    // ---- C: distance-weighted argmax over this keypoint's heatmap
    const float ky = s_kc[0];
    const float kx = s_kc[1];
    const float* hmap = g_hmhp + k * NPOS;
    {
        float bv = -1e30f; int bi = 0x7fffffff;
        #pragma unroll
        for (int i = 0; i < NPOS / 256; i++) {
            int p = tid + i * 256;
            float sig = fast_sig(__ldg(&hmap[p]));
            int py = p / FT;
            float dy = (float)py - ky;
            float dx = (float)(p - py * FT) - kx;
            float s = __fdividef(sig, sqrtf(dy * dy + dx * dx) + DELTA);
            if (s > bv || (s == bv && p < bi)) { bv = s; bi = p; }
        }
        #pragma unroll
        for (int off = 16; off; off >>= 1) {
            float ov = __shfl_down_sync(0xffffffffu, bv, off);
            int   oi = __shfl_down_sync(0xffffffffu, bi, off);
            if (ov > bv || (ov == bv && oi < bi)) { bv = ov; bi = oi; }
        }
        if (lane == 0) { s_v[wid] = bv; s_i[wid] = bi; }
        __syncthreads();
        if (tid == 0) {
            float xv = s_v[0]; int xi = s_i[0];
            #pragma unroll
            for (int w = 1; w < 8; w++) {
                if (s_v[w] > xv || (s_v[w] == xv && s_i[w] < xi)) {
                    xv = s_v[w]; xi = s_i[w];
                }
            }
            s_top = xi;
        }
        __syncthreads();
    }
    const int top = s_top;
    const int ty  = top / FT, tx = top % FT;

    // ---- D: hp_offset head at the winner (channels 2k, 2k+1) + outputs
    if (tid < C)
        s_y[tid] = dw_at(x, off_dw_w, off_dw_b, tid, ty, tx);
    __syncthreads();
    if (tid < HC) {
        float a = off_b1[tid];
        #pragma unroll
        for (int kk = 0; kk < C; kk++) a += __ldg(&off_w1[tid * C + kk]) * s_y[kk];
        s_z[tid] = fmaxf(a, 0.f);
    }
    __syncthreads();
    if (wid < 2) {
        int oc = 2 * k + wid;
        float a = __ldg(&off_w2[oc * HC + lane])      * s_z[lane]
                + __ldg(&off_w2[oc * HC + lane + 32]) * s_z[lane + 32]
                + __ldg(&off_w2[oc * HC + lane + 64]) * s_z[lane + 64];
        #pragma unroll
        for (int off = 16; off; off >>= 1)
            a += __shfl_down_sync(0xffffffffu, a, off);
        if (lane == 0) {
            float base = wid ? (float)tx : (float)ty;
            out[k * 3 + wid] = (a + off_b2[oc] + base) * OUT_SCALE;
        }
    }
    if (tid == 64)   // precise sigmoid for reported confidence
        out[k * 3 + 2] = 1.0f / (1.0f + expf(-hmap[top]));

    // ---- completion: 17th finisher resets counters for graph replay
    __syncthreads();
    if (tid == 0) {
        int d = atomicAdd(&g_done, 1);
        if (d == 16) {
            g_count = 0;
            g_done  = 0;
            __threadfence();
        }
    }
}

// ---------------------------------------------------------------------------
extern "C" void kernel_launch(void* const* d_in, const int* in_sizes, int n_in,
                              void* d_out, int out_size)
{
    fused_kernel<<<NBLK, 256>>>(
        (const float*)d_in[0],
        (const float*)d_in[1],  (const float*)d_in[2],
        (const float*)d_in[3],  (const float*)d_in[4],
        (const float*)d_in[5],  (const float*)d_in[6],
        (const float*)d_in[7],  (const float*)d_in[8],
        (const float*)d_in[9],  (const float*)d_in[10],
        (const float*)d_in[11], (const float*)d_in[12],
        (const float*)d_in[13], (const float*)d_in[14],
        (const float*)d_in[15], (const float*)d_in[16],
        (const float*)d_in[17], (const float*)d_in[18],
        (const float*)d_in[19], (const float*)d_in[20],
        (const float*)d_in[21], (const float*)d_in[22],
        (const float*)d_in[23], (const float*)d_in[24],
        (float*)d_out);
}